// round 9
// baseline (speedup 1.0000x reference)
#include <cuda_runtime.h>

#define H      512
#define NC     64
#define NS     5
#define NQ     15
#define NROWS  1280

__device__ float g_att[NROWS * H];

// MUFU hardware tanh (measured ~rt16 per SMSP).
__device__ __forceinline__ float tanh_approx(float x) {
    float y;
    asm("tanh.approx.f32 %0, %1;" : "=f"(y) : "f"(x));
    return y;
}

// FMA-pipe rational tanh (continued-fraction [5/6]):
// tanh(x) ~= x*(10395 + 1260u + 21u^2) / (10395 + 4725u + 210u^2 + u^3), u=x^2.
// err < 1e-6 for |x|<3, < 2.2e-5 at 3, < 2.1e-4 at 4. Inputs here have
// std ~0.33, so |x|>4 is vanishingly rare. Cost: ~8 FMA-pipe ops + 1 MUFU RCP.
__device__ __forceinline__ float tanh_poly(float x) {
    const float u = x * x;
    float n = fmaf(21.0f, u, 1260.0f);
    n = fmaf(n, u, 10395.0f);
    float d = fmaf(u + 210.0f, u, 4725.0f);
    d = fmaf(d, u, 10395.0f);
    return __fdividef(x * n, d);   // FMUL + MUFU.RCP + FMUL
}

// ---------------------------------------------------------------------------
// Kernel 1 (FROZEN): g_att = X @ W^T + b
// 64(m) x 32(n) tile, 128 threads, 4x4 micro-tile, BK=16.
// ---------------------------------------------------------------------------
__global__ __launch_bounds__(128) void gemm_xwt(const float* __restrict__ X,
                                                const float* __restrict__ W,
                                                const float* __restrict__ bias) {
    __shared__ float As[16][68];
    __shared__ float Bs[16][36];
    const int t  = threadIdx.x;
    const int tx = t & 7;
    const int ty = t >> 3;
    const int m0 = blockIdx.y * 64;
    const int n0 = blockIdx.x * 32;
    const int lr = t >> 2;
    const int lk = (t & 3) << 2;

    float acc[4][4] = {};

    for (int kk = 0; kk < H; kk += 16) {
        float4 a0 = *(const float4*)&X[(m0 + lr) * H + kk + lk];
        float4 a1 = *(const float4*)&X[(m0 + lr + 32) * H + kk + lk];
        float4 bv = *(const float4*)&W[(n0 + lr) * H + kk + lk];
        As[lk + 0][lr] = a0.x; As[lk + 1][lr] = a0.y;
        As[lk + 2][lr] = a0.z; As[lk + 3][lr] = a0.w;
        As[lk + 0][lr + 32] = a1.x; As[lk + 1][lr + 32] = a1.y;
        As[lk + 2][lr + 32] = a1.z; As[lk + 3][lr + 32] = a1.w;
        Bs[lk + 0][lr] = bv.x; Bs[lk + 1][lr] = bv.y;
        Bs[lk + 2][lr] = bv.z; Bs[lk + 3][lr] = bv.w;
        __syncthreads();
        #pragma unroll
        for (int k = 0; k < 16; k++) {
            float4 a4 = *(const float4*)&As[k][ty << 2];
            float4 b4 = *(const float4*)&Bs[k][tx << 2];
            float ar[4] = {a4.x, a4.y, a4.z, a4.w};
            float br[4] = {b4.x, b4.y, b4.z, b4.w};
            #pragma unroll
            for (int i = 0; i < 4; i++)
                #pragma unroll
                for (int j = 0; j < 4; j++)
                    acc[i][j] = fmaf(ar[i], br[j], acc[i][j]);
        }
        __syncthreads();
    }

    #pragma unroll
    for (int i = 0; i < 4; i++) {
        const int r = m0 + (ty << 2) + i;
        #pragma unroll
        for (int j = 0; j < 4; j++) {
            const int n = n0 + (tx << 2) + j;
            g_att[r * H + n] = acc[i][j] + bias[n];
        }
    }
}

// ---------------------------------------------------------------------------
// Kernel 2: R8 structure (measured 67.4us, tanh-MUFU-floor-bound), with the
// tanh work SPLIT 50/50 between the MUFU pipe (x,y components) and an
// FMA-pipe rational (z,w components) to equalize both pipes at ~12 cyc/elem.
// ---------------------------------------------------------------------------
__global__ __launch_bounds__(256, 2) void proto_attn(const float* __restrict__ X,
                                                     float* __restrict__ out) {
    const int c    = blockIdx.x;
    const int qb   = blockIdx.y;
    const int t    = threadIdx.x;
    const int warp = t >> 5;
    const int lane = t & 31;

    __shared__ float4 sA[NS * 128];   // s_att rows of class c
    __shared__ float4 sS[NS * 128];   // raw support rows of class c

    const float4* attv = (const float4*)g_att;
    const float4* xv   = (const float4*)X;

    for (int i = t; i < NS * 128; i += 256) {
        const int s   = i >> 7;
        const int off = i & 127;
        const int row = c * 20 + s;
        sA[i] = attv[row * 128 + off];
        sS[i] = xv[row * 128 + off];
    }
    __syncthreads();

    const int qc = qb * 8 + warp;

    for (int j = 0; j < NQ; j++) {
        const int row = qc * 20 + NS + j;
        const float4* qa = attv + row * 128;

        float acc[NS] = {0.f, 0.f, 0.f, 0.f, 0.f};
        #pragma unroll
        for (int i = 0; i < 4; i++) {
            const float4 a = qa[lane + i * 32];
            #pragma unroll
            for (int s = 0; s < NS; s++) {
                const float4 b = sA[s * 128 + lane + i * 32];
                // x,y -> MUFU tanh; z,w -> FMA-pipe rational: both pipes busy.
                acc[s] += tanh_approx(a.x * b.x);
                acc[s] += tanh_approx(a.y * b.y);
                acc[s] += tanh_poly(a.z * b.z);
                acc[s] += tanh_poly(a.w * b.w);
            }
        }
        #pragma unroll
        for (int s = 0; s < NS; s++) {
            #pragma unroll
            for (int o = 16; o > 0; o >>= 1)
                acc[s] += __shfl_xor_sync(0xffffffffu, acc[s], o);
        }

        // softmax over the 5 support scores
        float m = acc[0];
        #pragma unroll
        for (int s = 1; s < NS; s++) m = fmaxf(m, acc[s]);
        float w[NS];
        float sum = 0.f;
        #pragma unroll
        for (int s = 0; s < NS; s++) { w[s] = __expf(acc[s] - m); sum += w[s]; }
        const float inv = __fdividef(1.0f, sum);
        #pragma unroll
        for (int s = 0; s < NS; s++) w[s] *= inv;

        // proto & dist
        const float4* qx = xv + row * 128;
        float d = 0.f;
        #pragma unroll
        for (int i = 0; i < 4; i++) {
            const float4 qv = qx[lane + i * 32];
            float px = 0.f, py = 0.f, pz = 0.f, pw = 0.f;
            #pragma unroll
            for (int s = 0; s < NS; s++) {
                const float4 sv = sS[s * 128 + lane + i * 32];
                px = fmaf(w[s], sv.x, px);
                py = fmaf(w[s], sv.y, py);
                pz = fmaf(w[s], sv.z, pz);
                pw = fmaf(w[s], sv.w, pw);
            }
            const float dx = px - qv.x, dy = py - qv.y;
            const float dz = pz - qv.z, dw = pw - qv.w;
            d += dx * dx + dy * dy + dz * dz + dw * dw;
        }
        #pragma unroll
        for (int o = 16; o > 0; o >>= 1)
            d += __shfl_xor_sync(0xffffffffu, d, o);

        if (lane == 0) {
            const int q = qc * NQ + j;
            out[q * NC + c] = d;
        }
    }
}

extern "C" void kernel_launch(void* const* d_in, const int* in_sizes, int n_in,
                              void* d_out, int out_size) {
    const float* x = (const float*)d_in[0];
    const float* W = (const float*)d_in[1];
    const float* b = (const float*)d_in[2];
    float* out = (float*)d_out;

    gemm_xwt<<<dim3(H / 32, NROWS / 64), 128>>>(x, W, b);
    proto_attn<<<dim3(NC, 8), 256>>>(x, out);
}

// round 10
// speedup vs baseline: 1.1598x; 1.1598x over previous
#include <cuda_runtime.h>
#include <cstdint>

#define H      512
#define NC     64
#define NS     5
#define NQ     15
#define NROWS  1280

__device__ float g_att[NROWS * H];

__device__ __forceinline__ uint32_t pack_f16x2(float hi, float lo) {
    uint32_t r;
    asm("cvt.rn.f16x2.f32 %0, %1, %2;" : "=r"(r) : "f"(hi), "f"(lo));
    return r;
}

// ---------------------------------------------------------------------------
// Kernel 1 (FROZEN): g_att = X @ W^T + b
// 64(m) x 32(n) tile, 128 threads, 4x4 micro-tile, BK=16.
// ---------------------------------------------------------------------------
__global__ __launch_bounds__(128) void gemm_xwt(const float* __restrict__ X,
                                                const float* __restrict__ W,
                                                const float* __restrict__ bias) {
    __shared__ float As[16][68];
    __shared__ float Bs[16][36];
    const int t  = threadIdx.x;
    const int tx = t & 7;
    const int ty = t >> 3;
    const int m0 = blockIdx.y * 64;
    const int n0 = blockIdx.x * 32;
    const int lr = t >> 2;
    const int lk = (t & 3) << 2;

    float acc[4][4] = {};

    for (int kk = 0; kk < H; kk += 16) {
        float4 a0 = *(const float4*)&X[(m0 + lr) * H + kk + lk];
        float4 a1 = *(const float4*)&X[(m0 + lr + 32) * H + kk + lk];
        float4 bv = *(const float4*)&W[(n0 + lr) * H + kk + lk];
        As[lk + 0][lr] = a0.x; As[lk + 1][lr] = a0.y;
        As[lk + 2][lr] = a0.z; As[lk + 3][lr] = a0.w;
        As[lk + 0][lr + 32] = a1.x; As[lk + 1][lr + 32] = a1.y;
        As[lk + 2][lr + 32] = a1.z; As[lk + 3][lr + 32] = a1.w;
        Bs[lk + 0][lr] = bv.x; Bs[lk + 1][lr] = bv.y;
        Bs[lk + 2][lr] = bv.z; Bs[lk + 3][lr] = bv.w;
        __syncthreads();
        #pragma unroll
        for (int k = 0; k < 16; k++) {
            float4 a4 = *(const float4*)&As[k][ty << 2];
            float4 b4 = *(const float4*)&Bs[k][tx << 2];
            float ar[4] = {a4.x, a4.y, a4.z, a4.w};
            float br[4] = {b4.x, b4.y, b4.z, b4.w};
            #pragma unroll
            for (int i = 0; i < 4; i++)
                #pragma unroll
                for (int j = 0; j < 4; j++)
                    acc[i][j] = fmaf(ar[i], br[j], acc[i][j]);
        }
        __syncthreads();
    }

    #pragma unroll
    for (int i = 0; i < 4; i++) {
        const int r = m0 + (ty << 2) + i;
        #pragma unroll
        for (int j = 0; j < 4; j++) {
            const int n = n0 + (tx << 2) + j;
            g_att[r * H + n] = acc[i][j] + bias[n];
        }
    }
}

// ---------------------------------------------------------------------------
// Kernel 2: R8 structure, scores phase switched to f16x2 hardware tanh:
// one MUFU op = 2 tanh -> MUFU cycles halved (the measured binding pipe).
// Products in f16 (HMUL2), pairwise f16 fold (HADD2), then f32 accumulation.
// Support att rows staged in SMEM pre-packed as f16x2.
// ---------------------------------------------------------------------------
__global__ __launch_bounds__(256, 2) void proto_attn(const float* __restrict__ X,
                                                     float* __restrict__ out) {
    const int c    = blockIdx.x;
    const int qb   = blockIdx.y;
    const int t    = threadIdx.x;
    const int warp = t >> 5;
    const int lane = t & 31;

    __shared__ uint2  sAh[NS * 128];   // s_att rows of class c, packed f16x2 pairs
    __shared__ float4 sS [NS * 128];   // raw support rows of class c (f32, proto)

    const float4* attv = (const float4*)g_att;
    const float4* xv   = (const float4*)X;

    for (int i = t; i < NS * 128; i += 256) {
        const int s   = i >> 7;
        const int off = i & 127;
        const int row = c * 20 + s;
        const float4 v = attv[row * 128 + off];
        sAh[i] = make_uint2(pack_f16x2(v.y, v.x), pack_f16x2(v.w, v.z));
        sS[i]  = xv[row * 128 + off];
    }
    __syncthreads();

    const int qc = qb * 8 + warp;

    for (int j = 0; j < NQ; j++) {
        const int row = qc * 20 + NS + j;
        const float4* qa = attv + row * 128;

        float accA[NS] = {0.f, 0.f, 0.f, 0.f, 0.f};
        float accB[NS] = {0.f, 0.f, 0.f, 0.f, 0.f};
        #pragma unroll
        for (int i = 0; i < 4; i++) {
            const float4 a = qa[lane + i * 32];
            const uint32_t q01 = pack_f16x2(a.y, a.x);
            const uint32_t q23 = pack_f16x2(a.w, a.z);
            #pragma unroll
            for (int s = 0; s < NS; s++) {
                const uint2 sv = sAh[s * 128 + lane + i * 32];
                uint32_t p0, p1, r0, r1, rr;
                asm("mul.rn.f16x2 %0, %1, %2;" : "=r"(p0) : "r"(q01), "r"(sv.x));
                asm("mul.rn.f16x2 %0, %1, %2;" : "=r"(p1) : "r"(q23), "r"(sv.y));
                asm("tanh.approx.f16x2 %0, %1;" : "=r"(r0) : "r"(p0));
                asm("tanh.approx.f16x2 %0, %1;" : "=r"(r1) : "r"(p1));
                asm("add.rn.f16x2 %0, %1, %2;" : "=r"(rr) : "r"(r0), "r"(r1));
                float f0, f1;
                asm("{\n\t.reg .b16 l, h;\n\t"
                    "mov.b32 {l, h}, %2;\n\t"
                    "cvt.f32.f16 %0, l;\n\t"
                    "cvt.f32.f16 %1, h;\n\t}"
                    : "=f"(f0), "=f"(f1) : "r"(rr));
                accA[s] += f0;
                accB[s] += f1;
            }
        }

        float acc[NS];
        #pragma unroll
        for (int s = 0; s < NS; s++) {
            acc[s] = accA[s] + accB[s];
            #pragma unroll
            for (int o = 16; o > 0; o >>= 1)
                acc[s] += __shfl_xor_sync(0xffffffffu, acc[s], o);
        }

        // softmax over the 5 support scores
        float m = acc[0];
        #pragma unroll
        for (int s = 1; s < NS; s++) m = fmaxf(m, acc[s]);
        float w[NS];
        float sum = 0.f;
        #pragma unroll
        for (int s = 0; s < NS; s++) { w[s] = __expf(acc[s] - m); sum += w[s]; }
        const float inv = __fdividef(1.0f, sum);
        #pragma unroll
        for (int s = 0; s < NS; s++) w[s] *= inv;

        // proto & dist (f32, unchanged)
        const float4* qx = xv + row * 128;
        float d = 0.f;
        #pragma unroll
        for (int i = 0; i < 4; i++) {
            const float4 qv = qx[lane + i * 32];
            float px = 0.f, py = 0.f, pz = 0.f, pw = 0.f;
            #pragma unroll
            for (int s = 0; s < NS; s++) {
                const float4 sv = sS[s * 128 + lane + i * 32];
                px = fmaf(w[s], sv.x, px);
                py = fmaf(w[s], sv.y, py);
                pz = fmaf(w[s], sv.z, pz);
                pw = fmaf(w[s], sv.w, pw);
            }
            const float dx = px - qv.x, dy = py - qv.y;
            const float dz = pz - qv.z, dw = pw - qv.w;
            d += dx * dx + dy * dy + dz * dz + dw * dw;
        }
        #pragma unroll
        for (int o = 16; o > 0; o >>= 1)
            d += __shfl_xor_sync(0xffffffffu, d, o);

        if (lane == 0) {
            const int q = qc * NQ + j;
            out[q * NC + c] = d;
        }
    }
}

extern "C" void kernel_launch(void* const* d_in, const int* in_sizes, int n_in,
                              void* d_out, int out_size) {
    const float* x = (const float*)d_in[0];
    const float* W = (const float*)d_in[1];
    const float* b = (const float*)d_in[2];
    float* out = (float*)d_out;

    gemm_xwt<<<dim3(H / 32, NROWS / 64), 128>>>(x, W, b);
    proto_attn<<<dim3(NC, 8), 256>>>(x, out);
}